// round 16
// baseline (speedup 1.0000x reference)
#include <cuda_runtime.h>
#include <cuda_fp16.h>
#include <stdint.h>

#define BB 4
#define SS 2048
#define DD 1024
#define MQKV (BB*SS)   // 8192

#define BM 128
#define BKT 32
#define PITCH 40                         // fp16 elems per smem row (80B rows)
#define A_PLANE (BM*PITCH*2)             // 10240 B
#define STAGES 3

// --- wide config (Y 3-term + V 1-term mega): tile 128x256, 512 threads ---
#define W_BN 256
#define B_PLANE (W_BN*PITCH*2)              // 20480 B
#define YV_STAGE (2*A_PLANE + 2*B_PLANE)    // 61440
#define YV_SMEM (STAGES*YV_STAGE)           // 184320
#define V1_STAGE (A_PLANE + B_PLANE)        // 30720

// --- narrow config: tile 128x128, 256 threads ---
#define N_BN 128
#define G3_STAGE (4*A_PLANE)                // 40960
#define G3_SMEM (STAGES*G3_STAGE)           // 122880
// int8 score: plane = 128 rows x 80 bytes (64 data + 16 pad), BK = 64 bytes
#define S8_PITCHB 80
#define S8_PLANE (BM*S8_PITCHB)             // 10240 B
#define S8_STAGE (2*S8_PLANE)               // 20480
#define S8_SMEM (STAGES*S8_STAGE)           // 61440
#define S8_BK 64

#define Y_BLOCKS ((MQKV/BM)*(DD/W_BN))      // 256
#define V_BLOCKS ((MQKV/BM)*(DD/W_BN))      // 256
#define KSPLIT 4
#define KCHUNK (DD/KSPLIT)                  // 256

#define CMAX 128
#define MARGIN 14.0f
#define FB_MARGIN 10.0f

#define Q8SCALE 21.166666f                  // 127/6
#define Q8INV2  (6.0f/127.0f)*(6.0f/127.0f)

// ---------------- scratch ----------------
__device__ __half g_Xhi[(size_t)MQKV*DD], g_Xlo[(size_t)MQKV*DD];
__device__ signed char g_X8[(size_t)MQKV*DD];
__device__ __half g_Wqhi[(size_t)DD*DD], g_Wqlo[(size_t)DD*DD];
__device__ __half g_Wkhi[(size_t)DD*DD], g_Wklo[(size_t)DD*DD];
__device__ __half g_Wvthi[(size_t)DD*DD], g_Wvtlo[(size_t)DD*DD];
__device__ float  g_Gpart[(size_t)KSPLIT*DD*DD];
__device__ __half g_Gthi[(size_t)DD*DD], g_Gtlo[(size_t)DD*DD];
__device__ __half g_Yhi[(size_t)MQKV*DD], g_Ylo[(size_t)MQKV*DD];
__device__ signed char g_Y8[(size_t)MQKV*DD];
__device__ float  g_Vf [(size_t)MQKV*DD];
__device__ __half g_P  [(size_t)BB*SS*SS];

// ---------------- PTX helpers ----------------
__device__ __forceinline__ uint32_t s2u(const void* p){ return (uint32_t)__cvta_generic_to_shared(p); }
__device__ __forceinline__ void cp16(uint32_t d, const void* s){
    asm volatile("cp.async.cg.shared.global [%0], [%1], 16;\n" :: "r"(d), "l"(s));
}
__device__ __forceinline__ void cpcommit(){ asm volatile("cp.async.commit_group;\n"); }
template<int N> __device__ __forceinline__ void cpwait(){ asm volatile("cp.async.wait_group %0;\n" :: "n"(N)); }

#define LDSM4(r, addr) \
    asm volatile("ldmatrix.sync.aligned.m8n8.x4.shared.b16 {%0,%1,%2,%3}, [%4];\n" \
        : "=r"((r)[0]), "=r"((r)[1]), "=r"((r)[2]), "=r"((r)[3]) : "r"(addr))

#define MMA16816(d, a0,a1,a2,a3, b0,b1) \
    asm volatile("mma.sync.aligned.m16n8k16.row.col.f32.f16.f16.f32 " \
        "{%0,%1,%2,%3}, {%4,%5,%6,%7}, {%8,%9}, {%0,%1,%2,%3};\n" \
        : "+f"((d)[0]), "+f"((d)[1]), "+f"((d)[2]), "+f"((d)[3]) \
        : "r"(a0), "r"(a1), "r"(a2), "r"(a3), "r"(b0), "r"(b1))

#define MMAS8(d, a0,a1,a2,a3, b0,b1) \
    asm volatile("mma.sync.aligned.m16n8k32.row.col.s32.s8.s8.s32 " \
        "{%0,%1,%2,%3}, {%4,%5,%6,%7}, {%8,%9}, {%0,%1,%2,%3};\n" \
        : "+r"((d)[0]), "+r"((d)[1]), "+r"((d)[2]), "+r"((d)[3]) \
        : "r"(a0), "r"(a1), "r"(a2), "r"(a3), "r"(b0), "r"(b1))

__device__ __forceinline__ void split2(float x, float y, __half2& h, __half2& l){
    h.x = __float2half_rn(x); h.y = __float2half_rn(y);
    l.x = __float2half_rn(x - __half2float(h.x));
    l.y = __float2half_rn(y - __half2float(h.y));
}

__device__ __forceinline__ int q8(float x){
    float v = fminf(fmaxf(x * Q8SCALE, -127.f), 127.f);
    return __float2int_rn(v);
}

// ---------------------------------------------------------------------------
// G^T partials: 3-term split GEMM, narrow tile, K-chunked over blockIdx.z.
// ---------------------------------------------------------------------------
__global__ __launch_bounds__(256, 1)
void g_gemm_part(const __half* __restrict__ Ahi, const __half* __restrict__ Alo,
                 const __half* __restrict__ Bhi, const __half* __restrict__ Blo,
                 float* __restrict__ Cpart)
{
    extern __shared__ __half smbuf[];
    const int tid  = threadIdx.x, lane = tid & 31, warp = tid >> 5;
    const int m_w  = (warp & 1) * 64;
    const int n_w  = (warp >> 1) * 32;
    const int m0   = blockIdx.y * BM;
    const int n0   = blockIdx.x * N_BN;
    const int z    = blockIdx.z;

    const __half* pA[2] = { Ahi + (long long)m0*DD, Alo + (long long)m0*DD };
    const __half* pB[2] = { Bhi + (long long)n0*DD, Blo + (long long)n0*DD };

    const uint32_t sm0 = s2u(smbuf);
    const int lrow0 = tid >> 2,         lc0 = (tid & 3) * 8;
    const int lrow1 = (tid + 256) >> 2, lc1 = (tid & 3) * 8;
    auto load_stage = [&](int s, int kt){
        const uint32_t b = sm0 + (uint32_t)s * G3_STAGE;
        const long long ko = (long long)z * KCHUNK + (long long)kt * BKT;
        #pragma unroll
        for (int pl = 0; pl < 4; ++pl){
            const __half* src = (pl < 2) ? pA[pl] : pB[pl - 2];
            const uint32_t dst = b + (uint32_t)pl * A_PLANE;
            cp16(dst + (lrow0*PITCH + lc0)*2, src + (long long)lrow0*DD + ko + lc0);
            cp16(dst + (lrow1*PITCH + lc1)*2, src + (long long)lrow1*DD + ko + lc1);
        }
        cpcommit();
    };

    float acc[4][4][4];
    #pragma unroll
    for (int a=0;a<4;a++)
        #pragma unroll
        for (int b=0;b<4;b++)
            #pragma unroll
            for (int c=0;c<4;c++) acc[a][b][c] = 0.f;

    uint32_t aoff[4], boff[2];
    #pragma unroll
    for (int mt=0; mt<4; ++mt)
        aoff[mt] = ((m_w + mt*16 + (lane & 15))*PITCH + ((lane >> 4) << 3)) * 2;
    #pragma unroll
    for (int p=0; p<2; ++p)
        boff[p]  = ((n_w + p*16 + (lane & 7) + ((lane >> 4) << 3))*PITCH + (((lane >> 3) & 1) << 3)) * 2;

    const int nk = KCHUNK / BKT;   // 8
    load_stage(0, 0);
    load_stage(1, 1);

    for (int t = 0; t < nk; ++t){
        if (t == nk - 1) cpwait<0>(); else cpwait<1>();
        __syncthreads();
        if (t + 2 < nk) load_stage((t + 2) % STAGES, t + 2);

        const uint32_t b   = sm0 + (uint32_t)(t % STAGES) * G3_STAGE;
        const uint32_t aHi = b, aLo = b + A_PLANE;
        const uint32_t bHi = b + 2*A_PLANE, bLo = b + 3*A_PLANE;

        #pragma unroll
        for (int ks = 0; ks < BKT; ks += 16){
            const uint32_t kb = ks*2;
            uint32_t bh[2][4], bl[2][4];
            #pragma unroll
            for (int p=0; p<2; p++) LDSM4(bh[p], bHi + boff[p] + kb);
            #pragma unroll
            for (int p=0; p<2; p++) LDSM4(bl[p], bLo + boff[p] + kb);
            uint32_t ah[4][4], al[4][4];
            #pragma unroll
            for (int mt=0; mt<4; mt++){ LDSM4(ah[mt], aHi + aoff[mt] + kb); LDSM4(al[mt], aLo + aoff[mt] + kb); }
            #pragma unroll
            for (int mt=0; mt<4; mt++)
                #pragma unroll
                for (int nt=0; nt<4; nt++){
                    const int p = nt >> 1, h = (nt & 1) * 2;
                    MMA16816(acc[mt][nt], ah[mt][0],ah[mt][1],ah[mt][2],ah[mt][3], bh[p][h], bh[p][h+1]);
                    MMA16816(acc[mt][nt], ah[mt][0],ah[mt][1],ah[mt][2],ah[mt][3], bl[p][h], bl[p][h+1]);
                    MMA16816(acc[mt][nt], al[mt][0],al[mt][1],al[mt][2],al[mt][3], bh[p][h], bh[p][h+1]);
                }
        }
    }

    float* C = Cpart + (long long)z * DD * DD;
    #pragma unroll
    for (int mt=0; mt<4; mt++){
        #pragma unroll
        for (int nt=0; nt<4; nt++){
            const int r = m0 + m_w + mt*16 + (lane >> 2);
            const int c = n0 + n_w + nt*8  + (lane & 3)*2;
            *(float2*)&C[(long long)r*DD + c]     = make_float2(acc[mt][nt][0], acc[mt][nt][1]);
            *(float2*)&C[(long long)(r+8)*DD + c] = make_float2(acc[mt][nt][2], acc[mt][nt][3]);
        }
    }
}

__global__ __launch_bounds__(256)
void g_reduce_split(const float* __restrict__ Gpart,
                    __half* __restrict__ hi, __half* __restrict__ lo)
{
    const long long i = ((long long)blockIdx.x*256 + threadIdx.x)*2;
    const long long n = (long long)DD*DD;
    float2 s = make_float2(0.f, 0.f);
    #pragma unroll
    for (int z = 0; z < KSPLIT; ++z){
        float2 v = *(const float2*)&Gpart[(long long)z*n + i];
        s.x += v.x; s.y += v.y;
    }
    __half2 h, l;
    split2(s.x, s.y, h, l);
    *(__half2*)&hi[i] = h;
    *(__half2*)&lo[i] = l;
}

// ---------------------------------------------------------------------------
// Mega Y+V kernel, 512 threads, tile 128x256.
// Y path also emits int8-quantized Y8 for the selection GEMM.
// ---------------------------------------------------------------------------
__global__ __launch_bounds__(512, 1)
void yv_gemm(const __half* __restrict__ Xhi, const __half* __restrict__ Xlo,
             const __half* __restrict__ Gthi, const __half* __restrict__ Gtlo,
             const __half* __restrict__ Wvthi,
             __half* __restrict__ Yhi, __half* __restrict__ Ylo,
             signed char* __restrict__ Y8,
             float* __restrict__ Vf)
{
    extern __shared__ __half smbuf[];
    const int tid  = threadIdx.x, lane = tid & 31, warp = tid >> 5;
    const int m_w  = (warp & 1) * 64;
    const int n_w  = (warp >> 1) * 32;
    const uint32_t sm0 = s2u(smbuf);

    const int arow = tid >> 2,          ac  = (tid & 3) * 8;
    const int brow0 = tid >> 2,         bc0 = (tid & 3) * 8;
    const int brow1 = (tid + 512) >> 2, bc1 = (tid & 3) * 8;

    uint32_t aoff[4], boff[2];
    #pragma unroll
    for (int mt=0; mt<4; ++mt)
        aoff[mt] = ((m_w + mt*16 + (lane & 15))*PITCH + ((lane >> 4) << 3)) * 2;
    #pragma unroll
    for (int p=0; p<2; ++p)
        boff[p]  = ((n_w + p*16 + (lane & 7) + ((lane >> 4) << 3))*PITCH + (((lane >> 3) & 1) << 3)) * 2;

    const int id = blockIdx.x;
    const int nk = DD / BKT;  // 32

    if (id < Y_BLOCKS){
        const int bx = id & 3, by = id >> 2;
        const int m0 = by * BM, n0 = bx * W_BN;
        const __half* pAh = Xhi + (long long)m0*DD;
        const __half* pAl = Xlo + (long long)m0*DD;
        const __half* pBh = Gthi + (long long)n0*DD;
        const __half* pBl = Gtlo + (long long)n0*DD;

        auto load_stage = [&](int s, int kt){
            const uint32_t b = sm0 + (uint32_t)s * YV_STAGE;
            const long long ko = (long long)kt * BKT;
            cp16(b +             (arow*PITCH + ac)*2,  pAh + (long long)arow*DD + ko + ac);
            cp16(b + A_PLANE   + (arow*PITCH + ac)*2,  pAl + (long long)arow*DD + ko + ac);
            cp16(b + 2*A_PLANE + (brow0*PITCH + bc0)*2, pBh + (long long)brow0*DD + ko + bc0);
            cp16(b + 2*A_PLANE + (brow1*PITCH + bc1)*2, pBh + (long long)brow1*DD + ko + bc1);
            cp16(b + 2*A_PLANE + B_PLANE + (brow0*PITCH + bc0)*2, pBl + (long long)brow0*DD + ko + bc0);
            cp16(b + 2*A_PLANE + B_PLANE + (brow1*PITCH + bc1)*2, pBl + (long long)brow1*DD + ko + bc1);
            cpcommit();
        };

        float acc[4][4][4];
        #pragma unroll
        for (int a=0;a<4;a++)
            #pragma unroll
            for (int b=0;b<4;b++)
                #pragma unroll
                for (int c=0;c<4;c++) acc[a][b][c] = 0.f;

        load_stage(0, 0);
        load_stage(1, 1);

        for (int t = 0; t < nk; ++t){
            if (t == nk - 1) cpwait<0>(); else cpwait<1>();
            __syncthreads();
            if (t + 2 < nk) load_stage((t + 2) % STAGES, t + 2);

            const uint32_t b   = sm0 + (uint32_t)(t % STAGES) * YV_STAGE;
            const uint32_t aHi = b, aLo = b + A_PLANE;
            const uint32_t bHi = b + 2*A_PLANE, bLo = b + 2*A_PLANE + B_PLANE;

            #pragma unroll
            for (int ks = 0; ks < BKT; ks += 16){
                const uint32_t kb = ks*2;
                uint32_t bh[2][4], bl[2][4];
                #pragma unroll
                for (int p=0; p<2; p++) LDSM4(bh[p], bHi + boff[p] + kb);
                #pragma unroll
                for (int p=0; p<2; p++) LDSM4(bl[p], bLo + boff[p] + kb);

                uint32_t ah[2][4], al[2][4];
                LDSM4(ah[0], aHi + aoff[0] + kb);
                LDSM4(al[0], aLo + aoff[0] + kb);
                #pragma unroll
                for (int mt=0; mt<4; mt++){
                    const int cur = mt & 1, nxt = cur ^ 1;
                    if (mt < 3){
                        LDSM4(ah[nxt], aHi + aoff[mt+1] + kb);
                        LDSM4(al[nxt], aLo + aoff[mt+1] + kb);
                    }
                    #pragma unroll
                    for (int nt=0; nt<4; nt++){
                        const int p = nt >> 1, h = (nt & 1) * 2;
                        MMA16816(acc[mt][nt], ah[cur][0],ah[cur][1],ah[cur][2],ah[cur][3], bh[p][h], bh[p][h+1]);
                        MMA16816(acc[mt][nt], ah[cur][0],ah[cur][1],ah[cur][2],ah[cur][3], bl[p][h], bl[p][h+1]);
                        MMA16816(acc[mt][nt], al[cur][0],al[cur][1],al[cur][2],al[cur][3], bh[p][h], bh[p][h+1]);
                    }
                }
            }
        }

        #pragma unroll
        for (int mt=0; mt<4; mt++){
            #pragma unroll
            for (int nt=0; nt<4; nt++){
                const int r = m0 + m_w + mt*16 + (lane >> 2);
                const int c = n0 + n_w + nt*8  + (lane & 3)*2;
                #pragma unroll
                for (int half = 0; half < 2; ++half){
                    const float x = acc[mt][nt][half*2 + 0];
                    const float y = acc[mt][nt][half*2 + 1];
                    const long long off = (long long)(r + half*8)*DD + c;
                    __half2 hv, lv;
                    split2(x, y, hv, lv);
                    *(__half2*)&Yhi[off] = hv;
                    *(__half2*)&Ylo[off] = lv;
                    unsigned short pk = (unsigned short)((q8(x) & 0xFF) | ((q8(y) & 0xFF) << 8));
                    *(unsigned short*)&Y8[off] = pk;
                }
            }
        }
    } else {
        const int id2 = id - Y_BLOCKS;
        const int bx = id2 & 3, by = id2 >> 2;
        const int m0 = by * BM, n0 = bx * W_BN;
        const __half* pA = Xhi + (long long)m0*DD;
        const __half* pB = Wvthi + (long long)n0*DD;

        auto load_stage = [&](int s, int kt){
            const uint32_t b = sm0 + (uint32_t)s * V1_STAGE;
            const long long ko = (long long)kt * BKT;
            cp16(b +           (arow*PITCH + ac)*2,   pA + (long long)arow*DD + ko + ac);
            cp16(b + A_PLANE + (brow0*PITCH + bc0)*2, pB + (long long)brow0*DD + ko + bc0);
            cp16(b + A_PLANE + (brow1*PITCH + bc1)*2, pB + (long long)brow1*DD + ko + bc1);
            cpcommit();
        };

        float acc[4][4][4];
        #pragma unroll
        for (int a=0;a<4;a++)
            #pragma unroll
            for (int b=0;b<4;b++)
                #pragma unroll
                for (int c=0;c<4;c++) acc[a][b][c] = 0.f;

        load_stage(0, 0);
        load_stage(1, 1);

        for (int t = 0; t < nk; ++t){
            if (t == nk - 1) cpwait<0>(); else cpwait<1>();
            __syncthreads();
            if (t + 2 < nk) load_stage((t + 2) % STAGES, t + 2);

            const uint32_t b   = sm0 + (uint32_t)(t % STAGES) * V1_STAGE;
            const uint32_t aHi = b, bHi = b + A_PLANE;

            #pragma unroll
            for (int ks = 0; ks < BKT; ks += 16){
                const uint32_t kb = ks*2;
                uint32_t bh[2][4], ah[4][4];
                #pragma unroll
                for (int p=0; p<2; p++)  LDSM4(bh[p], bHi + boff[p] + kb);
                #pragma unroll
                for (int mt=0; mt<4; mt++) LDSM4(ah[mt], aHi + aoff[mt] + kb);
                #pragma unroll
                for (int mt=0; mt<4; mt++)
                    #pragma unroll
                    for (int nt=0; nt<4; nt++){
                        const int p = nt >> 1, h = (nt & 1) * 2;
                        MMA16816(acc[mt][nt], ah[mt][0],ah[mt][1],ah[mt][2],ah[mt][3], bh[p][h], bh[p][h+1]);
                    }
            }
        }

        #pragma unroll
        for (int mt=0; mt<4; mt++){
            #pragma unroll
            for (int nt=0; nt<4; nt++){
                const int r = m0 + m_w + mt*16 + (lane >> 2);
                const int c = n0 + n_w + nt*8  + (lane & 3)*2;
                *(float2*)&Vf[(long long)r*DD + c]     = make_float2(acc[mt][nt][0], acc[mt][nt][1]);
                *(float2*)&Vf[(long long)(r+8)*DD + c] = make_float2(acc[mt][nt][2], acc[mt][nt][3]);
            }
        }
    }
}

// ---------------------------------------------------------------------------
// INT8 score GEMM: 256 threads, tile 128x128, 2 CTA/SM. s8 x s8 -> s32,
// k32 MMA (2x K per instruction). Epilogue scales by (6/127)^2 -> fp16 P.
// Identical byte addressing to the fp16 path (80B pitch rows, 16B chunks).
// ---------------------------------------------------------------------------
__global__ __launch_bounds__(256)
void score_gemm_s8(const signed char* __restrict__ A, const signed char* __restrict__ B,
                   __half* __restrict__ Ch, int M, int N,
                   long long sA, long long sB, long long sC)
{
    extern __shared__ __align__(16) signed char smbuf8[];
    const int tid  = threadIdx.x, lane = tid & 31, warp = tid >> 5;
    const int m_w  = (warp & 1) * 64;
    const int n_w  = (warp >> 1) * 32;
    const int m0   = blockIdx.y * BM;
    const int n0   = blockIdx.x * N_BN;
    const long long z = blockIdx.z;

    const signed char* pA = A + z*sA + (long long)m0*DD;
    const signed char* pB = B + z*sB + (long long)n0*DD;

    const uint32_t sm0 = s2u(smbuf8);
    // 512 chunks/plane (128 rows x 4x16B); 2 per thread per plane
    const int lrow0 = tid >> 2,         lc0 = (tid & 3) * 16;
    const int lrow1 = (tid + 256) >> 2, lc1 = (tid & 3) * 16;
    auto load_stage = [&](int s, int kt){
        const uint32_t b = sm0 + (uint32_t)s * S8_STAGE;
        const long long ko = (long long)kt * S8_BK;
        cp16(b + lrow0*S8_PITCHB + lc0,            pA + (long long)lrow0*DD + ko + lc0);
        cp16(b + lrow1*S8_PITCHB + lc1,            pA + (long long)lrow1*DD + ko + lc1);
        cp16(b + S8_PLANE + lrow0*S8_PITCHB + lc0, pB + (long long)lrow0*DD + ko + lc0);
        cp16(b + S8_PLANE + lrow1*S8_PITCHB + lc1, pB + (long long)lrow1*DD + ko + lc1);
        cpcommit();
    };

    int acc[4][4][4];
    #pragma unroll
    for (int a=0;a<4;a++)
        #pragma unroll
        for (int b=0;b<4;b++)
            #pragma unroll
            for (int c=0;c<4;c++) acc[a][b][c] = 0;

    // byte offsets (same structure as fp16 path)
    uint32_t aoff[4], boff[2];
    #pragma unroll
    for (int mt=0; mt<4; ++mt)
        aoff[mt] = (m_w + mt*16 + (lane & 15))*S8_PITCHB + ((lane >> 4) << 4);
    #pragma unroll
    for (int p=0; p<2; ++p)
        boff[p]  = (n_w + p*16 + (lane & 7) + ((lane >> 4) << 3))*S8_PITCHB + (((lane >> 3) & 1) << 4);

    const int nk = DD / S8_BK;   // 16
    load_stage(0, 0);
    load_stage(1, 1);

    for (int t = 0; t < nk; ++t){
        if (t == nk - 1) cpwait<0>(); else cpwait<1>();
        __syncthreads();
        if (t + 2 < nk) load_stage((t + 2) % STAGES, t + 2);

        const uint32_t b   = sm0 + (uint32_t)(t % STAGES) * S8_STAGE;
        const uint32_t aB = b, bB = b + S8_PLANE;

        #pragma unroll
        for (int ks = 0; ks < S8_BK; ks += 32){
            const uint32_t kb = ks;        // bytes
            uint32_t bh[2][4], ah[4][4];
            #pragma unroll
            for (int p=0; p<2; p++)  LDSM4(bh[p], bB + boff[p] + kb);
            #pragma unroll
            for (int mt=0; mt<4; mt++) LDSM4(ah[mt], aB + aoff[mt] + kb);
            #pragma unroll
            for (int mt=0; mt<4; mt++)
                #pragma unroll
                for (int nt=0; nt<4; nt++){
                    const int p = nt >> 1, h = (nt & 1) * 2;
                    MMAS8(acc[mt][nt], ah[mt][0],ah[mt][1],ah[mt][2],ah[mt][3], bh[p][h], bh[p][h+1]);
                }
        }
    }

    const long long Cz = z * sC;
    const float s = Q8INV2;
    #pragma unroll
    for (int mt=0; mt<4; mt++){
        #pragma unroll
        for (int nt=0; nt<4; nt++){
            const int r = m0 + m_w + mt*16 + (lane >> 2);
            const int c = n0 + n_w + nt*8  + (lane & 3)*2;
            __half2 v0, v1;
            v0.x = __float2half_rn((float)acc[mt][nt][0] * s);
            v0.y = __float2half_rn((float)acc[mt][nt][1] * s);
            v1.x = __float2half_rn((float)acc[mt][nt][2] * s);
            v1.y = __float2half_rn((float)acc[mt][nt][3] * s);
            *(__half2*)&Ch[Cz + (long long)r*N + c]     = v0;
            *(__half2*)&Ch[Cz + (long long)(r+8)*N + c] = v1;
        }
    }
}

// ---------------------------------------------------------------------------
// Fused: candidate select -> exact fp32 rescore (y_i . x_j) -> softmax -> ctx.
// ---------------------------------------------------------------------------
__global__ __launch_bounds__(256)
void attn_sparse(const __half* __restrict__ P,
                 const __half* __restrict__ Yhi, const __half* __restrict__ Ylo,
                 const __half* __restrict__ Xhi, const __half* __restrict__ Xlo,
                 const float* __restrict__ Vf, float* __restrict__ out)
{
    __shared__ float s_red[8];
    __shared__ int   s_cnt;
    __shared__ int   s_idx[CMAX];
    __shared__ float s_sc[CMAX];
    __shared__ float s_w[CMAX];

    const int row  = blockIdx.x;
    const int b    = row >> 11;
    const int tid  = threadIdx.x, lane = tid & 31, warp = tid >> 5;
    const __half2* prow2 = (const __half2*)(P + (long long)row * SS);

    float m = -3.402823466e+38f;
    #pragma unroll
    for (int it = 0; it < SS/512; ++it){
        float2 v = __half22float2(prow2[tid + it*256]);
        m = fmaxf(m, fmaxf(v.x, v.y));
    }
    #pragma unroll
    for (int s = 16; s > 0; s >>= 1) m = fmaxf(m, __shfl_xor_sync(0xffffffffu, m, s));
    if (lane == 0) s_red[warp] = m;
    if (tid == 0) s_cnt = 0;
    __syncthreads();
    float mall = s_red[0];
    #pragma unroll
    for (int w = 1; w < 8; ++w) mall = fmaxf(mall, s_red[w]);

    {
        const float thr = mall - MARGIN;
        #pragma unroll
        for (int it = 0; it < SS/512; ++it){
            const int j = tid + it*256;
            float2 v = __half22float2(prow2[j]);
            if (v.x > thr){
                int slot = atomicAdd(&s_cnt, 1);
                if (slot < CMAX) s_idx[slot] = 2*j;
            }
            if (v.y > thr){
                int slot = atomicAdd(&s_cnt, 1);
                if (slot < CMAX) s_idx[slot] = 2*j + 1;
            }
        }
    }
    __syncthreads();
    const int total = s_cnt;
    __syncthreads();
    if (total > CMAX){
        if (tid == 0) s_cnt = 0;
        __syncthreads();
        const float thr2 = mall - FB_MARGIN;
        #pragma unroll
        for (int it = 0; it < SS/512; ++it){
            const int j = tid + it*256;
            float2 v = __half22float2(prow2[j]);
            if (v.x > thr2){
                int slot = atomicAdd(&s_cnt, 1);
                if (slot < CMAX) s_idx[slot] = 2*j;
            }
            if (v.y > thr2){
                int slot = atomicAdd(&s_cnt, 1);
                if (slot < CMAX) s_idx[slot] = 2*j + 1;
            }
        }
        __syncthreads();
    }
    const int cnt = min(s_cnt, CMAX);

    const __half2* qh = (const __half2*)(Yhi + (long long)row*DD);
    const __half2* ql = (const __half2*)(Ylo + (long long)row*DD);
    for (int c = warp; c < cnt; c += 8){
        const long long krow = ((long long)b*SS + s_idx[c]) * DD;
        const __half2* kh = (const __half2*)(Xhi + krow);
        const __half2* kl = (const __half2*)(Xlo + krow);
        float s = 0.f;
        #pragma unroll 4
        for (int d = lane; d < DD/2; d += 32){
            float2 q2h = __half22float2(qh[d]), q2l = __half22float2(ql[d]);
            float2 k2h = __half22float2(kh[d]), k2l = __half22float2(kl[d]);
            s += (q2h.x + q2l.x) * (k2h.x + k2l.x)
               + (q2h.y + q2l.y) * (k2h.y + k2l.y);
        }
        #pragma unroll
        for (int sh = 16; sh > 0; sh >>= 1) s += __shfl_xor_sync(0xffffffffu, s, sh);
        if (lane == 0) s_sc[c] = s;
    }
    __syncthreads();

    if (tid == 0){
        float mx = s_sc[0];
        for (int c = 1; c < cnt; ++c) mx = fmaxf(mx, s_sc[c]);
        float sum = 0.f;
        for (int c = 0; c < cnt; ++c){ float e = expf(s_sc[c] - mx); s_w[c] = e; sum += e; }
        float inv = 1.f / sum;
        for (int c = 0; c < cnt; ++c) s_w[c] *= inv;
    }
    __syncthreads();

    const int d0 = tid * 4;
    float4 acc = make_float4(0.f, 0.f, 0.f, 0.f);
    for (int c = 0; c < cnt; ++c){
        const float w = s_w[c];
        const float4 v = *(const float4*)&Vf[((long long)b*SS + s_idx[c])*DD + d0];
        acc.x += w * v.x; acc.y += w * v.y; acc.z += w * v.z; acc.w += w * v.w;
    }
    *(float4*)&out[(long long)row*DD + d0] = acc;
}

// ---------------------------------------------------------------------------
__global__ __launch_bounds__(256)
void split_plain_x(const float* __restrict__ x, __half* __restrict__ hi,
                   __half* __restrict__ lo, signed char* __restrict__ q,
                   long long n)
{
    long long i = ((long long)blockIdx.x*256 + threadIdx.x)*4;
    if (i >= n) return;
    float4 v = *(const float4*)&x[i];
    __half2 h0,h1,l0,l1;
    split2(v.x, v.y, h0, l0);
    split2(v.z, v.w, h1, l1);
    *(__half2*)&hi[i]   = h0;  *(__half2*)&hi[i+2] = h1;
    *(__half2*)&lo[i]   = l0;  *(__half2*)&lo[i+2] = l1;
    uint32_t pk = (uint32_t)(q8(v.x) & 0xFF) | ((uint32_t)(q8(v.y) & 0xFF) << 8)
                | ((uint32_t)(q8(v.z) & 0xFF) << 16) | ((uint32_t)(q8(v.w) & 0xFF) << 24);
    *(uint32_t*)&q[i] = pk;
}

__global__ __launch_bounds__(256)
void split_plain(const float* __restrict__ x, __half* __restrict__ hi,
                 __half* __restrict__ lo, long long n)
{
    long long i = ((long long)blockIdx.x*256 + threadIdx.x)*4;
    if (i >= n) return;
    float4 v = *(const float4*)&x[i];
    __half2 h0,h1,l0,l1;
    split2(v.x, v.y, h0, l0);
    split2(v.z, v.w, h1, l1);
    *(__half2*)&hi[i]   = h0;  *(__half2*)&hi[i+2] = h1;
    *(__half2*)&lo[i]   = l0;  *(__half2*)&lo[i+2] = l1;
}

__global__ __launch_bounds__(256)
void transpose_split(const float* __restrict__ src, __half* __restrict__ hi,
                     __half* __restrict__ lo)
{
    __shared__ float t[32][33];
    const int c0 = blockIdx.x*32, r0 = blockIdx.y*32;
    const int tx = threadIdx.x & 31, ty = threadIdx.x >> 5;
    #pragma unroll
    for (int i=0;i<4;i++){
        int y = ty + i*8;
        t[y][tx] = src[(long long)(r0+y)*DD + c0 + tx];
    }
    __syncthreads();
    #pragma unroll
    for (int i=0;i<4;i++){
        int y = ty + i*8;
        float v = t[tx][y];
        __half h = __float2half_rn(v);
        __half l = __float2half_rn(v - __half2float(h));
        long long o = (long long)(c0+y)*DD + r0 + tx;
        hi[o] = h; lo[o] = l;
    }
}

// ---------------------------------------------------------------------------
extern "C" void kernel_launch(void* const* d_in, const int* in_sizes, int n_in,
                              void* d_out, int out_size)
{
    const float* X  = (const float*)d_in[0];
    const float* Wq = (const float*)d_in[1];
    const float* Wk = (const float*)d_in[2];
    const float* Wv = (const float*)d_in[3];
    float* out = (float*)d_out;

    __half *Xhi,*Xlo,*Wqhi,*Wqlo,*Wkhi,*Wklo,*Wvthi,*Wvtlo,*Gthi,*Gtlo,*Yhi,*Ylo,*P;
    signed char *X8,*Y8;
    float *Gpart,*Vf;
    cudaGetSymbolAddress((void**)&Xhi,  g_Xhi);   cudaGetSymbolAddress((void**)&Xlo,  g_Xlo);
    cudaGetSymbolAddress((void**)&X8,   g_X8);
    cudaGetSymbolAddress((void**)&Wqhi, g_Wqhi);  cudaGetSymbolAddress((void**)&Wqlo, g_Wqlo);
    cudaGetSymbolAddress((void**)&Wkhi, g_Wkhi);  cudaGetSymbolAddress((void**)&Wklo, g_Wklo);
    cudaGetSymbolAddress((void**)&Wvthi,g_Wvthi); cudaGetSymbolAddress((void**)&Wvtlo,g_Wvtlo);
    cudaGetSymbolAddress((void**)&Gpart,g_Gpart);
    cudaGetSymbolAddress((void**)&Gthi, g_Gthi);  cudaGetSymbolAddress((void**)&Gtlo, g_Gtlo);
    cudaGetSymbolAddress((void**)&Yhi,  g_Yhi);   cudaGetSymbolAddress((void**)&Ylo,  g_Ylo);
    cudaGetSymbolAddress((void**)&Y8,   g_Y8);
    cudaGetSymbolAddress((void**)&Vf,   g_Vf);
    cudaGetSymbolAddress((void**)&P,    g_P);

    cudaFuncSetAttribute(g_gemm_part,  cudaFuncAttributeMaxDynamicSharedMemorySize, G3_SMEM);
    cudaFuncSetAttribute(yv_gemm,      cudaFuncAttributeMaxDynamicSharedMemorySize, YV_SMEM);
    cudaFuncSetAttribute(score_gemm_s8,cudaFuncAttributeMaxDynamicSharedMemorySize, S8_SMEM);

    const long long nX = (long long)MQKV*DD;
    const long long nW = (long long)DD*DD;

    // 1) splits: X (hi/lo + int8), Wq/Wk plain, Wv transposed
    split_plain_x<<<(unsigned)(nX/4/256), 256>>>(X, Xhi, Xlo, X8, nX);
    split_plain<<<(unsigned)(nW/4/256), 256>>>(Wq, Wqhi, Wqlo, nW);
    split_plain<<<(unsigned)(nW/4/256), 256>>>(Wk, Wkhi, Wklo, nW);
    {
        dim3 g(DD/32, DD/32, 1), b(256);
        transpose_split<<<g, b>>>(Wv, Wvthi, Wvtlo);
    }

    // 2) G^T partials then reduce+split
    {
        dim3 g(DD/N_BN, DD/BM, KSPLIT), b(256);
        g_gemm_part<<<g, b, G3_SMEM>>>(Wkhi, Wklo, Wqhi, Wqlo, Gpart);
    }
    g_reduce_split<<<(unsigned)(nW/2/256), 256>>>(Gpart, Gthi, Gtlo);

    // 3) mega launch: Y (3-term, +int8 quantize) + V (1-term)
    yv_gemm<<<Y_BLOCKS + V_BLOCKS, 512, YV_SMEM>>>(Xhi, Xlo, Gthi, Gtlo, Wvthi,
                                                   Yhi, Ylo, Y8, Vf);

    // 4) approximate scores: int8 Y8 * X8^T per batch (k32 MMA)
    {
        dim3 g(SS/N_BN, SS/BM, BB), b(256);
        score_gemm_s8<<<g, b, S8_SMEM>>>(Y8, X8, P, SS, SS,
                                         (long long)SS*DD, (long long)SS*DD, (long long)SS*SS);
    }

    // 5) fused candidate-select + exact rescore + softmax + sparse context
    attn_sparse<<<MQKV, 256>>>(P, Yhi, Ylo, Xhi, Xlo, Vf, out);
}

// round 17
// speedup vs baseline: 1.2602x; 1.2602x over previous
#include <cuda_runtime.h>
#include <cuda_fp16.h>
#include <stdint.h>

#define BB 4
#define SS 2048
#define DD 1024
#define MQKV (BB*SS)   // 8192

#define BM 128
#define BKT 32
#define PITCH 40                         // fp16 elems per smem row (80B rows)
#define A_PLANE (BM*PITCH*2)             // 10240 B
#define STAGES 3

// --- wide config (Y 3-term + V 1-term mega): tile 128x256, 512 threads ---
#define W_BN 256
#define B_PLANE (W_BN*PITCH*2)              // 20480 B
#define YV_STAGE (2*A_PLANE + 2*B_PLANE)    // 61440
#define YV_SMEM (STAGES*YV_STAGE)           // 184320
#define V1_STAGE (A_PLANE + B_PLANE)        // 30720

// --- narrow config (G partials, score): tile 128x128, 256 threads ---
#define N_BN 128
#define G3_STAGE (4*A_PLANE)                // 40960
#define G3_SMEM (STAGES*G3_STAGE)           // 122880
#define SC_STAGE (2*A_PLANE)                // 20480
#define SC_SMEM (STAGES*SC_STAGE)           // 61440

#define Y_BLOCKS ((MQKV/BM)*(DD/W_BN))      // 256
#define V_BLOCKS ((MQKV/BM)*(DD/W_BN))      // 256
#define KSPLIT 4
#define KCHUNK (DD/KSPLIT)                  // 256

#define CMAX 128
#define MARGIN 14.0f
#define FB_MARGIN 10.0f

// ---------------- scratch ----------------
__device__ __half g_Xhi[(size_t)MQKV*DD], g_Xlo[(size_t)MQKV*DD];
__device__ __half g_Wqhi[(size_t)DD*DD], g_Wqlo[(size_t)DD*DD];       // plain split
__device__ __half g_Wkhi[(size_t)DD*DD], g_Wklo[(size_t)DD*DD];       // plain split
__device__ __half g_Wvthi[(size_t)DD*DD], g_Wvtlo[(size_t)DD*DD];     // Wv^T split
__device__ float  g_Gpart[(size_t)KSPLIT*DD*DD];                      // G^T partials
__device__ __half g_Gthi[(size_t)DD*DD], g_Gtlo[(size_t)DD*DD];       // G^T split
__device__ __half g_Yhi[(size_t)MQKV*DD], g_Ylo[(size_t)MQKV*DD];     // Y = X*G
__device__ float  g_Vf [(size_t)MQKV*DD];
__device__ __half g_P  [(size_t)BB*SS*SS];                            // fp16 approx scores

// ---------------- PTX helpers ----------------
__device__ __forceinline__ uint32_t s2u(const void* p){ return (uint32_t)__cvta_generic_to_shared(p); }
__device__ __forceinline__ void cp16(uint32_t d, const void* s){
    asm volatile("cp.async.cg.shared.global [%0], [%1], 16;\n" :: "r"(d), "l"(s));
}
__device__ __forceinline__ void cpcommit(){ asm volatile("cp.async.commit_group;\n"); }
template<int N> __device__ __forceinline__ void cpwait(){ asm volatile("cp.async.wait_group %0;\n" :: "n"(N)); }

#define LDSM4(r, addr) \
    asm volatile("ldmatrix.sync.aligned.m8n8.x4.shared.b16 {%0,%1,%2,%3}, [%4];\n" \
        : "=r"((r)[0]), "=r"((r)[1]), "=r"((r)[2]), "=r"((r)[3]) : "r"(addr))

#define MMA16816(d, a0,a1,a2,a3, b0,b1) \
    asm volatile("mma.sync.aligned.m16n8k16.row.col.f32.f16.f16.f32 " \
        "{%0,%1,%2,%3}, {%4,%5,%6,%7}, {%8,%9}, {%0,%1,%2,%3};\n" \
        : "+f"((d)[0]), "+f"((d)[1]), "+f"((d)[2]), "+f"((d)[3]) \
        : "r"(a0), "r"(a1), "r"(a2), "r"(a3), "r"(b0), "r"(b1))

__device__ __forceinline__ void split2(float x, float y, __half2& h, __half2& l){
    h.x = __float2half_rn(x); h.y = __float2half_rn(y);
    l.x = __float2half_rn(x - __half2float(h.x));
    l.y = __float2half_rn(y - __half2float(h.y));
}

// ---------------------------------------------------------------------------
// G^T partials: 3-term split GEMM, narrow tile, K-chunked over blockIdx.z.
// Gt[d'][d] = sum_e Wk[d',e]*Wq[d,e]
// ---------------------------------------------------------------------------
__global__ __launch_bounds__(256, 1)
void g_gemm_part(const __half* __restrict__ Ahi, const __half* __restrict__ Alo,
                 const __half* __restrict__ Bhi, const __half* __restrict__ Blo,
                 float* __restrict__ Cpart)
{
    extern __shared__ __half smbuf[];
    const int tid  = threadIdx.x, lane = tid & 31, warp = tid >> 5;
    const int m_w  = (warp & 1) * 64;
    const int n_w  = (warp >> 1) * 32;
    const int m0   = blockIdx.y * BM;
    const int n0   = blockIdx.x * N_BN;
    const int z    = blockIdx.z;

    const __half* pA[2] = { Ahi + (long long)m0*DD, Alo + (long long)m0*DD };
    const __half* pB[2] = { Bhi + (long long)n0*DD, Blo + (long long)n0*DD };

    const uint32_t sm0 = s2u(smbuf);
    const int lrow0 = tid >> 2,         lc0 = (tid & 3) * 8;
    const int lrow1 = (tid + 256) >> 2, lc1 = (tid & 3) * 8;
    auto load_stage = [&](int s, int kt){
        const uint32_t b = sm0 + (uint32_t)s * G3_STAGE;
        const long long ko = (long long)z * KCHUNK + (long long)kt * BKT;
        #pragma unroll
        for (int pl = 0; pl < 4; ++pl){
            const __half* src = (pl < 2) ? pA[pl] : pB[pl - 2];
            const uint32_t dst = b + (uint32_t)pl * A_PLANE;
            cp16(dst + (lrow0*PITCH + lc0)*2, src + (long long)lrow0*DD + ko + lc0);
            cp16(dst + (lrow1*PITCH + lc1)*2, src + (long long)lrow1*DD + ko + lc1);
        }
        cpcommit();
    };

    float acc[4][4][4];
    #pragma unroll
    for (int a=0;a<4;a++)
        #pragma unroll
        for (int b=0;b<4;b++)
            #pragma unroll
            for (int c=0;c<4;c++) acc[a][b][c] = 0.f;

    uint32_t aoff[4], boff[2];
    #pragma unroll
    for (int mt=0; mt<4; ++mt)
        aoff[mt] = ((m_w + mt*16 + (lane & 15))*PITCH + ((lane >> 4) << 3)) * 2;
    #pragma unroll
    for (int p=0; p<2; ++p)
        boff[p]  = ((n_w + p*16 + (lane & 7) + ((lane >> 4) << 3))*PITCH + (((lane >> 3) & 1) << 3)) * 2;

    const int nk = KCHUNK / BKT;   // 8
    load_stage(0, 0);
    load_stage(1, 1);

    for (int t = 0; t < nk; ++t){
        if (t == nk - 1) cpwait<0>(); else cpwait<1>();
        __syncthreads();
        if (t + 2 < nk) load_stage((t + 2) % STAGES, t + 2);

        const uint32_t b   = sm0 + (uint32_t)(t % STAGES) * G3_STAGE;
        const uint32_t aHi = b, aLo = b + A_PLANE;
        const uint32_t bHi = b + 2*A_PLANE, bLo = b + 3*A_PLANE;

        #pragma unroll
        for (int ks = 0; ks < BKT; ks += 16){
            const uint32_t kb = ks*2;
            uint32_t bh[2][4], bl[2][4];
            #pragma unroll
            for (int p=0; p<2; p++) LDSM4(bh[p], bHi + boff[p] + kb);
            #pragma unroll
            for (int p=0; p<2; p++) LDSM4(bl[p], bLo + boff[p] + kb);
            uint32_t ah[4][4], al[4][4];
            #pragma unroll
            for (int mt=0; mt<4; mt++){ LDSM4(ah[mt], aHi + aoff[mt] + kb); LDSM4(al[mt], aLo + aoff[mt] + kb); }
            #pragma unroll
            for (int mt=0; mt<4; mt++)
                #pragma unroll
                for (int nt=0; nt<4; nt++){
                    const int p = nt >> 1, h = (nt & 1) * 2;
                    MMA16816(acc[mt][nt], ah[mt][0],ah[mt][1],ah[mt][2],ah[mt][3], bh[p][h], bh[p][h+1]);
                    MMA16816(acc[mt][nt], ah[mt][0],ah[mt][1],ah[mt][2],ah[mt][3], bl[p][h], bl[p][h+1]);
                    MMA16816(acc[mt][nt], al[mt][0],al[mt][1],al[mt][2],al[mt][3], bh[p][h], bh[p][h+1]);
                }
        }
    }

    float* C = Cpart + (long long)z * DD * DD;
    #pragma unroll
    for (int mt=0; mt<4; mt++){
        #pragma unroll
        for (int nt=0; nt<4; nt++){
            const int r = m0 + m_w + mt*16 + (lane >> 2);
            const int c = n0 + n_w + nt*8  + (lane & 3)*2;
            *(float2*)&C[(long long)r*DD + c]     = make_float2(acc[mt][nt][0], acc[mt][nt][1]);
            *(float2*)&C[(long long)(r+8)*DD + c] = make_float2(acc[mt][nt][2], acc[mt][nt][3]);
        }
    }
}

__global__ __launch_bounds__(256)
void g_reduce_split(const float* __restrict__ Gpart,
                    __half* __restrict__ hi, __half* __restrict__ lo)
{
    const long long i = ((long long)blockIdx.x*256 + threadIdx.x)*2;
    const long long n = (long long)DD*DD;
    float2 s = make_float2(0.f, 0.f);
    #pragma unroll
    for (int z = 0; z < KSPLIT; ++z){
        float2 v = *(const float2*)&Gpart[(long long)z*n + i];
        s.x += v.x; s.y += v.y;
    }
    __half2 h, l;
    split2(s.x, s.y, h, l);
    *(__half2*)&hi[i] = h;
    *(__half2*)&lo[i] = l;
}

// ---------------------------------------------------------------------------
// Mega Y+V kernel, 512 threads, tile 128x256.
// Blocks [0, Y_BLOCKS): Y = X*Gt (3-term split GEMM, split out).
// Blocks [Y_BLOCKS, +V_BLOCKS): V 1-term GEMM (fp32 out). Heavy first.
// ---------------------------------------------------------------------------
__global__ __launch_bounds__(512, 1)
void yv_gemm(const __half* __restrict__ Xhi, const __half* __restrict__ Xlo,
             const __half* __restrict__ Gthi, const __half* __restrict__ Gtlo,
             const __half* __restrict__ Wvthi,
             __half* __restrict__ Yhi, __half* __restrict__ Ylo,
             float* __restrict__ Vf)
{
    extern __shared__ __half smbuf[];
    const int tid  = threadIdx.x, lane = tid & 31, warp = tid >> 5;
    const int m_w  = (warp & 1) * 64;
    const int n_w  = (warp >> 1) * 32;
    const uint32_t sm0 = s2u(smbuf);

    const int arow = tid >> 2,          ac  = (tid & 3) * 8;
    const int brow0 = tid >> 2,         bc0 = (tid & 3) * 8;
    const int brow1 = (tid + 512) >> 2, bc1 = (tid & 3) * 8;

    uint32_t aoff[4], boff[2];
    #pragma unroll
    for (int mt=0; mt<4; ++mt)
        aoff[mt] = ((m_w + mt*16 + (lane & 15))*PITCH + ((lane >> 4) << 3)) * 2;
    #pragma unroll
    for (int p=0; p<2; ++p)
        boff[p]  = ((n_w + p*16 + (lane & 7) + ((lane >> 4) << 3))*PITCH + (((lane >> 3) & 1) << 3)) * 2;

    const int id = blockIdx.x;
    const int nk = DD / BKT;  // 32

    if (id < Y_BLOCKS){
        const int bx = id & 3, by = id >> 2;
        const int m0 = by * BM, n0 = bx * W_BN;
        const __half* pAh = Xhi + (long long)m0*DD;
        const __half* pAl = Xlo + (long long)m0*DD;
        const __half* pBh = Gthi + (long long)n0*DD;
        const __half* pBl = Gtlo + (long long)n0*DD;

        auto load_stage = [&](int s, int kt){
            const uint32_t b = sm0 + (uint32_t)s * YV_STAGE;
            const long long ko = (long long)kt * BKT;
            cp16(b +             (arow*PITCH + ac)*2,  pAh + (long long)arow*DD + ko + ac);
            cp16(b + A_PLANE   + (arow*PITCH + ac)*2,  pAl + (long long)arow*DD + ko + ac);
            cp16(b + 2*A_PLANE + (brow0*PITCH + bc0)*2, pBh + (long long)brow0*DD + ko + bc0);
            cp16(b + 2*A_PLANE + (brow1*PITCH + bc1)*2, pBh + (long long)brow1*DD + ko + bc1);
            cp16(b + 2*A_PLANE + B_PLANE + (brow0*PITCH + bc0)*2, pBl + (long long)brow0*DD + ko + bc0);
            cp16(b + 2*A_PLANE + B_PLANE + (brow1*PITCH + bc1)*2, pBl + (long long)brow1*DD + ko + bc1);
            cpcommit();
        };

        float acc[4][4][4];
        #pragma unroll
        for (int a=0;a<4;a++)
            #pragma unroll
            for (int b=0;b<4;b++)
                #pragma unroll
                for (int c=0;c<4;c++) acc[a][b][c] = 0.f;

        load_stage(0, 0);
        load_stage(1, 1);

        for (int t = 0; t < nk; ++t){
            if (t == nk - 1) cpwait<0>(); else cpwait<1>();
            __syncthreads();
            if (t + 2 < nk) load_stage((t + 2) % STAGES, t + 2);

            const uint32_t b   = sm0 + (uint32_t)(t % STAGES) * YV_STAGE;
            const uint32_t aHi = b, aLo = b + A_PLANE;
            const uint32_t bHi = b + 2*A_PLANE, bLo = b + 2*A_PLANE + B_PLANE;

            #pragma unroll
            for (int ks = 0; ks < BKT; ks += 16){
                const uint32_t kb = ks*2;
                uint32_t bh[2][4], bl[2][4];
                #pragma unroll
                for (int p=0; p<2; p++) LDSM4(bh[p], bHi + boff[p] + kb);
                #pragma unroll
                for (int p=0; p<2; p++) LDSM4(bl[p], bLo + boff[p] + kb);

                uint32_t ah[2][4], al[2][4];
                LDSM4(ah[0], aHi + aoff[0] + kb);
                LDSM4(al[0], aLo + aoff[0] + kb);
                #pragma unroll
                for (int mt=0; mt<4; mt++){
                    const int cur = mt & 1, nxt = cur ^ 1;
                    if (mt < 3){
                        LDSM4(ah[nxt], aHi + aoff[mt+1] + kb);
                        LDSM4(al[nxt], aLo + aoff[mt+1] + kb);
                    }
                    #pragma unroll
                    for (int nt=0; nt<4; nt++){
                        const int p = nt >> 1, h = (nt & 1) * 2;
                        MMA16816(acc[mt][nt], ah[cur][0],ah[cur][1],ah[cur][2],ah[cur][3], bh[p][h], bh[p][h+1]);
                        MMA16816(acc[mt][nt], ah[cur][0],ah[cur][1],ah[cur][2],ah[cur][3], bl[p][h], bl[p][h+1]);
                        MMA16816(acc[mt][nt], al[cur][0],al[cur][1],al[cur][2],al[cur][3], bh[p][h], bh[p][h+1]);
                    }
                }
            }
        }

        #pragma unroll
        for (int mt=0; mt<4; mt++){
            #pragma unroll
            for (int nt=0; nt<4; nt++){
                const int r = m0 + m_w + mt*16 + (lane >> 2);
                const int c = n0 + n_w + nt*8  + (lane & 3)*2;
                #pragma unroll
                for (int half = 0; half < 2; ++half){
                    const long long off = (long long)(r + half*8)*DD + c;
                    __half2 hv, lv;
                    split2(acc[mt][nt][half*2], acc[mt][nt][half*2+1], hv, lv);
                    *(__half2*)&Yhi[off] = hv;
                    *(__half2*)&Ylo[off] = lv;
                }
            }
        }
    } else {
        const int id2 = id - Y_BLOCKS;
        const int bx = id2 & 3, by = id2 >> 2;
        const int m0 = by * BM, n0 = bx * W_BN;
        const __half* pA = Xhi + (long long)m0*DD;
        const __half* pB = Wvthi + (long long)n0*DD;

        auto load_stage = [&](int s, int kt){
            const uint32_t b = sm0 + (uint32_t)s * V1_STAGE;
            const long long ko = (long long)kt * BKT;
            cp16(b +           (arow*PITCH + ac)*2,   pA + (long long)arow*DD + ko + ac);
            cp16(b + A_PLANE + (brow0*PITCH + bc0)*2, pB + (long long)brow0*DD + ko + bc0);
            cp16(b + A_PLANE + (brow1*PITCH + bc1)*2, pB + (long long)brow1*DD + ko + bc1);
            cpcommit();
        };

        float acc[4][4][4];
        #pragma unroll
        for (int a=0;a<4;a++)
            #pragma unroll
            for (int b=0;b<4;b++)
                #pragma unroll
                for (int c=0;c<4;c++) acc[a][b][c] = 0.f;

        load_stage(0, 0);
        load_stage(1, 1);

        for (int t = 0; t < nk; ++t){
            if (t == nk - 1) cpwait<0>(); else cpwait<1>();
            __syncthreads();
            if (t + 2 < nk) load_stage((t + 2) % STAGES, t + 2);

            const uint32_t b   = sm0 + (uint32_t)(t % STAGES) * V1_STAGE;
            const uint32_t aHi = b, bHi = b + A_PLANE;

            #pragma unroll
            for (int ks = 0; ks < BKT; ks += 16){
                const uint32_t kb = ks*2;
                uint32_t bh[2][4], ah[4][4];
                #pragma unroll
                for (int p=0; p<2; p++)  LDSM4(bh[p], bHi + boff[p] + kb);
                #pragma unroll
                for (int mt=0; mt<4; mt++) LDSM4(ah[mt], aHi + aoff[mt] + kb);
                #pragma unroll
                for (int mt=0; mt<4; mt++)
                    #pragma unroll
                    for (int nt=0; nt<4; nt++){
                        const int p = nt >> 1, h = (nt & 1) * 2;
                        MMA16816(acc[mt][nt], ah[mt][0],ah[mt][1],ah[mt][2],ah[mt][3], bh[p][h], bh[p][h+1]);
                    }
            }
        }

        #pragma unroll
        for (int mt=0; mt<4; mt++){
            #pragma unroll
            for (int nt=0; nt<4; nt++){
                const int r = m0 + m_w + mt*16 + (lane >> 2);
                const int c = n0 + n_w + nt*8  + (lane & 3)*2;
                *(float2*)&Vf[(long long)r*DD + c]     = make_float2(acc[mt][nt][0], acc[mt][nt][1]);
                *(float2*)&Vf[(long long)(r+8)*DD + c] = make_float2(acc[mt][nt][2], acc[mt][nt][3]);
            }
        }
    }
}

// ---------------------------------------------------------------------------
// Score GEMM: 256 threads, tile 128x128 (2 CTA/SM). 1-term Yhi*Xhi^T,
// fp32 accum, fp16 out. Row stride DD, z-batched.
// ---------------------------------------------------------------------------
__global__ __launch_bounds__(256)
void score_gemm(const __half* __restrict__ A, const __half* __restrict__ B,
                __half* __restrict__ Ch, int M, int N,
                long long sA, long long sB, long long sC)
{
    extern __shared__ __half smbuf[];
    const int tid  = threadIdx.x, lane = tid & 31, warp = tid >> 5;
    const int m_w  = (warp & 1) * 64;
    const int n_w  = (warp >> 1) * 32;
    const int m0   = blockIdx.y * BM;
    const int n0   = blockIdx.x * N_BN;
    const long long z = blockIdx.z;

    const __half* pA = A + z*sA + (long long)m0*DD;
    const __half* pB = B + z*sB + (long long)n0*DD;

    const uint32_t sm0 = s2u(smbuf);
    const int lrow0 = tid >> 2,         lc0 = (tid & 3) * 8;
    const int lrow1 = (tid + 256) >> 2, lc1 = (tid & 3) * 8;
    auto load_stage = [&](int s, int kt){
        const uint32_t b = sm0 + (uint32_t)s * SC_STAGE;
        const long long ko = (long long)kt * BKT;
        cp16(b + (lrow0*PITCH + lc0)*2,           pA + (long long)lrow0*DD + ko + lc0);
        cp16(b + (lrow1*PITCH + lc1)*2,           pA + (long long)lrow1*DD + ko + lc1);
        cp16(b + A_PLANE + (lrow0*PITCH + lc0)*2, pB + (long long)lrow0*DD + ko + lc0);
        cp16(b + A_PLANE + (lrow1*PITCH + lc1)*2, pB + (long long)lrow1*DD + ko + lc1);
        cpcommit();
    };

    float acc[4][4][4];
    #pragma unroll
    for (int a=0;a<4;a++)
        #pragma unroll
        for (int b=0;b<4;b++)
            #pragma unroll
            for (int c=0;c<4;c++) acc[a][b][c] = 0.f;

    uint32_t aoff[4], boff[2];
    #pragma unroll
    for (int mt=0; mt<4; ++mt)
        aoff[mt] = ((m_w + mt*16 + (lane & 15))*PITCH + ((lane >> 4) << 3)) * 2;
    #pragma unroll
    for (int p=0; p<2; ++p)
        boff[p]  = ((n_w + p*16 + (lane & 7) + ((lane >> 4) << 3))*PITCH + (((lane >> 3) & 1) << 3)) * 2;

    const int nk = DD / BKT;
    load_stage(0, 0);
    load_stage(1, 1);

    for (int t = 0; t < nk; ++t){
        if (t == nk - 1) cpwait<0>(); else cpwait<1>();
        __syncthreads();
        if (t + 2 < nk) load_stage((t + 2) % STAGES, t + 2);

        const uint32_t b   = sm0 + (uint32_t)(t % STAGES) * SC_STAGE;
        const uint32_t aHi = b, bHi = b + A_PLANE;

        #pragma unroll
        for (int ks = 0; ks < BKT; ks += 16){
            const uint32_t kb = ks*2;
            uint32_t bh[2][4], ah[4][4];
            #pragma unroll
            for (int p=0; p<2; p++)  LDSM4(bh[p], bHi + boff[p] + kb);
            #pragma unroll
            for (int mt=0; mt<4; mt++) LDSM4(ah[mt], aHi + aoff[mt] + kb);
            #pragma unroll
            for (int mt=0; mt<4; mt++)
                #pragma unroll
                for (int nt=0; nt<4; nt++){
                    const int p = nt >> 1, h = (nt & 1) * 2;
                    MMA16816(acc[mt][nt], ah[mt][0],ah[mt][1],ah[mt][2],ah[mt][3], bh[p][h], bh[p][h+1]);
                }
        }
    }

    const long long Cz = z * sC;
    #pragma unroll
    for (int mt=0; mt<4; mt++){
        #pragma unroll
        for (int nt=0; nt<4; nt++){
            const int r = m0 + m_w + mt*16 + (lane >> 2);
            const int c = n0 + n_w + nt*8  + (lane & 3)*2;
            __half2 v0, v1;
            v0.x = __float2half_rn(acc[mt][nt][0]); v0.y = __float2half_rn(acc[mt][nt][1]);
            v1.x = __float2half_rn(acc[mt][nt][2]); v1.y = __float2half_rn(acc[mt][nt][3]);
            *(__half2*)&Ch[Cz + (long long)r*N + c]     = v0;
            *(__half2*)&Ch[Cz + (long long)(r+8)*N + c] = v1;
        }
    }
}

// ---------------------------------------------------------------------------
// Fused: candidate select (margin 14, fallback 10 on overflow) -> exact fp32
// rescore (y_i . x_j from splits) -> exact softmax -> sparse context.
// ---------------------------------------------------------------------------
__global__ __launch_bounds__(256)
void attn_sparse(const __half* __restrict__ P,
                 const __half* __restrict__ Yhi, const __half* __restrict__ Ylo,
                 const __half* __restrict__ Xhi, const __half* __restrict__ Xlo,
                 const float* __restrict__ Vf, float* __restrict__ out)
{
    __shared__ float s_red[8];
    __shared__ int   s_cnt;
    __shared__ int   s_idx[CMAX];
    __shared__ float s_sc[CMAX];
    __shared__ float s_w[CMAX];

    const int row  = blockIdx.x;
    const int b    = row >> 11;
    const int tid  = threadIdx.x, lane = tid & 31, warp = tid >> 5;
    const __half2* prow2 = (const __half2*)(P + (long long)row * SS);

    float m = -3.402823466e+38f;
    #pragma unroll
    for (int it = 0; it < SS/512; ++it){
        float2 v = __half22float2(prow2[tid + it*256]);
        m = fmaxf(m, fmaxf(v.x, v.y));
    }
    #pragma unroll
    for (int s = 16; s > 0; s >>= 1) m = fmaxf(m, __shfl_xor_sync(0xffffffffu, m, s));
    if (lane == 0) s_red[warp] = m;
    if (tid == 0) s_cnt = 0;
    __syncthreads();
    float mall = s_red[0];
    #pragma unroll
    for (int w = 1; w < 8; ++w) mall = fmaxf(mall, s_red[w]);

    {
        const float thr = mall - MARGIN;
        #pragma unroll
        for (int it = 0; it < SS/512; ++it){
            const int j = tid + it*256;
            float2 v = __half22float2(prow2[j]);
            if (v.x > thr){
                int slot = atomicAdd(&s_cnt, 1);
                if (slot < CMAX) s_idx[slot] = 2*j;
            }
            if (v.y > thr){
                int slot = atomicAdd(&s_cnt, 1);
                if (slot < CMAX) s_idx[slot] = 2*j + 1;
            }
        }
    }
    __syncthreads();
    const int total = s_cnt;
    __syncthreads();
    if (total > CMAX){
        if (tid == 0) s_cnt = 0;
        __syncthreads();
        const float thr2 = mall - FB_MARGIN;
        #pragma unroll
        for (int it = 0; it < SS/512; ++it){
            const int j = tid + it*256;
            float2 v = __half22float2(prow2[j]);
            if (v.x > thr2){
                int slot = atomicAdd(&s_cnt, 1);
                if (slot < CMAX) s_idx[slot] = 2*j;
            }
            if (v.y > thr2){
                int slot = atomicAdd(&s_cnt, 1);
                if (slot < CMAX) s_idx[slot] = 2*j + 1;
            }
        }
        __syncthreads();
    }
    const int cnt = min(s_cnt, CMAX);

    const __half2* qh = (const __half2*)(Yhi + (long long)row*DD);
    const __half2* ql = (const __half2*)(Ylo + (long long)row*DD);
    for (int c = warp; c < cnt; c += 8){
        const long long krow = ((long long)b*SS + s_idx[c]) * DD;
        const __half2* kh = (const __half2*)(Xhi + krow);
        const __half2* kl = (const __half2*)(Xlo + krow);
        float s = 0.f;
        #pragma unroll 4
        for (int d = lane; d < DD/2; d += 32){
            float2 q2h = __half22float2(qh[d]), q2l = __half22float2(ql[d]);
            float2 k2h = __half22float2(kh[d]), k2l = __half22float2(kl[d]);
            s += (q2h.x + q2l.x) * (k2h.x + k2l.x)
               + (q2h.y + q2l.y) * (k2h.y + k2l.y);
        }
        #pragma unroll
        for (int sh = 16; sh > 0; sh >>= 1) s += __shfl_xor_sync(0xffffffffu, s, sh);
        if (lane == 0) s_sc[c] = s;
    }
    __syncthreads();

    if (tid == 0){
        float mx = s_sc[0];
        for (int c = 1; c < cnt; ++c) mx = fmaxf(mx, s_sc[c]);
        float sum = 0.f;
        for (int c = 0; c < cnt; ++c){ float e = expf(s_sc[c] - mx); s_w[c] = e; sum += e; }
        float inv = 1.f / sum;
        for (int c = 0; c < cnt; ++c) s_w[c] *= inv;
    }
    __syncthreads();

    const int d0 = tid * 4;
    float4 acc = make_float4(0.f, 0.f, 0.f, 0.f);
    for (int c = 0; c < cnt; ++c){
        const float w = s_w[c];
        const float4 v = *(const float4*)&Vf[((long long)b*SS + s_idx[c])*DD + d0];
        acc.x += w * v.x; acc.y += w * v.y; acc.z += w * v.z; acc.w += w * v.w;
    }
    *(float4*)&out[(long long)row*DD + d0] = acc;
}

// ---------------------------------------------------------------------------
__global__ __launch_bounds__(256)
void split_plain(const float* __restrict__ x, __half* __restrict__ hi,
                 __half* __restrict__ lo, long long n)
{
    long long i = ((long long)blockIdx.x*256 + threadIdx.x)*4;
    if (i >= n) return;
    float4 v = *(const float4*)&x[i];
    __half2 h0,h1,l0,l1;
    split2(v.x, v.y, h0, l0);
    split2(v.z, v.w, h1, l1);
    *(__half2*)&hi[i]   = h0;  *(__half2*)&hi[i+2] = h1;
    *(__half2*)&lo[i]   = l0;  *(__half2*)&lo[i+2] = l1;
}

// z-batched split of the two plain weight matrices (Wq, Wk)
__global__ __launch_bounds__(256)
void split_plain_w2(const float* __restrict__ W0, const float* __restrict__ W1,
                    __half* __restrict__ hi0, __half* __restrict__ lo0,
                    __half* __restrict__ hi1, __half* __restrict__ lo1)
{
    const float* x = (blockIdx.z == 0) ? W0 : W1;
    __half* hi = (blockIdx.z == 0) ? hi0 : hi1;
    __half* lo = (blockIdx.z == 0) ? lo0 : lo1;
    long long i = ((long long)blockIdx.x*256 + threadIdx.x)*4;
    float4 v = *(const float4*)&x[i];
    __half2 h0,h1,l0,l1;
    split2(v.x, v.y, h0, l0);
    split2(v.z, v.w, h1, l1);
    *(__half2*)&hi[i]   = h0;  *(__half2*)&hi[i+2] = h1;
    *(__half2*)&lo[i]   = l0;  *(__half2*)&lo[i+2] = l1;
}

__global__ __launch_bounds__(256)
void transpose_split(const float* __restrict__ src, __half* __restrict__ hi,
                     __half* __restrict__ lo)
{
    __shared__ float t[32][33];
    const int c0 = blockIdx.x*32, r0 = blockIdx.y*32;
    const int tx = threadIdx.x & 31, ty = threadIdx.x >> 5;
    #pragma unroll
    for (int i=0;i<4;i++){
        int y = ty + i*8;
        t[y][tx] = src[(long long)(r0+y)*DD + c0 + tx];
    }
    __syncthreads();
    #pragma unroll
    for (int i=0;i<4;i++){
        int y = ty + i*8;
        float v = t[tx][y];
        __half h = __float2half_rn(v);
        __half l = __float2half_rn(v - __half2float(h));
        long long o = (long long)(c0+y)*DD + r0 + tx;
        hi[o] = h; lo[o] = l;
    }
}

// ---------------------------------------------------------------------------
extern "C" void kernel_launch(void* const* d_in, const int* in_sizes, int n_in,
                              void* d_out, int out_size)
{
    const float* X  = (const float*)d_in[0];
    const float* Wq = (const float*)d_in[1];
    const float* Wk = (const float*)d_in[2];
    const float* Wv = (const float*)d_in[3];
    float* out = (float*)d_out;

    __half *Xhi,*Xlo,*Wqhi,*Wqlo,*Wkhi,*Wklo,*Wvthi,*Wvtlo,*Gthi,*Gtlo,*Yhi,*Ylo,*P;
    float *Gpart,*Vf;
    cudaGetSymbolAddress((void**)&Xhi,  g_Xhi);   cudaGetSymbolAddress((void**)&Xlo,  g_Xlo);
    cudaGetSymbolAddress((void**)&Wqhi, g_Wqhi);  cudaGetSymbolAddress((void**)&Wqlo, g_Wqlo);
    cudaGetSymbolAddress((void**)&Wkhi, g_Wkhi);  cudaGetSymbolAddress((void**)&Wklo, g_Wklo);
    cudaGetSymbolAddress((void**)&Wvthi,g_Wvthi); cudaGetSymbolAddress((void**)&Wvtlo,g_Wvtlo);
    cudaGetSymbolAddress((void**)&Gpart,g_Gpart);
    cudaGetSymbolAddress((void**)&Gthi, g_Gthi);  cudaGetSymbolAddress((void**)&Gtlo, g_Gtlo);
    cudaGetSymbolAddress((void**)&Yhi,  g_Yhi);   cudaGetSymbolAddress((void**)&Ylo,  g_Ylo);
    cudaGetSymbolAddress((void**)&Vf,   g_Vf);
    cudaGetSymbolAddress((void**)&P,    g_P);

    cudaFuncSetAttribute(g_gemm_part, cudaFuncAttributeMaxDynamicSharedMemorySize, G3_SMEM);
    cudaFuncSetAttribute(yv_gemm,     cudaFuncAttributeMaxDynamicSharedMemorySize, YV_SMEM);
    cudaFuncSetAttribute(score_gemm,  cudaFuncAttributeMaxDynamicSharedMemorySize, SC_SMEM);

    const long long nX = (long long)MQKV*DD;
    const long long nW = (long long)DD*DD;

    // 1) splits: X plain; Wq+Wk plain (one z-batched launch); Wv transposed
    split_plain<<<(unsigned)(nX/4/256), 256>>>(X, Xhi, Xlo, nX);
    {
        dim3 g((unsigned)(nW/4/256), 1, 2), b(256);
        split_plain_w2<<<g, b>>>(Wq, Wk, Wqhi, Wqlo, Wkhi, Wklo);
    }
    {
        dim3 g(DD/32, DD/32, 1), b(256);
        transpose_split<<<g, b>>>(Wv, Wvthi, Wvtlo);
    }

    // 2) G^T partials (K-split over z) then reduce+split
    {
        dim3 g(DD/N_BN, DD/BM, KSPLIT), b(256);
        g_gemm_part<<<g, b, G3_SMEM>>>(Wkhi, Wklo, Wqhi, Wqlo, Gpart);
    }
    g_reduce_split<<<(unsigned)(nW/2/256), 256>>>(Gpart, Gthi, Gtlo);

    // 3) mega launch: Y = X*Gt (3-term, split out) + V (1-term, fp32)
    yv_gemm<<<Y_BLOCKS + V_BLOCKS, 512, YV_SMEM>>>(Xhi, Xlo, Gthi, Gtlo, Wvthi,
                                                   Yhi, Ylo, Vf);

    // 4) approximate scores: Yhi * Xhi^T per batch (128x128, 2 CTA/SM)
    {
        dim3 g(SS/N_BN, SS/BM, BB), b(256);
        score_gemm<<<g, b, SC_SMEM>>>(Yhi, Xhi, P, SS, SS,
                                      (long long)SS*DD, (long long)SS*DD, (long long)SS*SS);
    }

    // 5) fused candidate-select + exact rescore + softmax + sparse context
    attn_sparse<<<MQKV, 256>>>(P, Yhi, Ylo, Xhi, Xlo, Vf, out);
}